// round 9
// baseline (speedup 1.0000x reference)
#include <cuda_runtime.h>
#include <cstdint>

#define NB 2048
#define NROWS (NB + 2)
#define TPB 256
#define GRID_EDGE 1184

__device__ double g_parts[2048];
__device__ unsigned int g_count = 0;
// LUT row = 128 floats (512B): [0:64) permuted (P0,P1) values, [64:128) slopes
// (next row - this row). Value float index: h*32 + j*4 + tt*2 + {0,1} for
// element m = 4j + (2h+tt) owned by lane j:
//   m <  8: P0 = ws[m]·GS,       P1 = ws[16+m]·GS·sqrt(3)   (g = S1=sum unit)
//   m >= 8: u=(m-8)/3: P0 = ws[24+u]·GS, P1 = ws[8+u]·GS    (g = unit[(m-8)%3])
__device__ __align__(16) float g_LUT[NROWS * 128];

// ---------------------------------------------------------------------------
__device__ __forceinline__ void compute_ws(int row, const float* sW1,
                                           const float* sW2r, float* ws) {
#pragma unroll
    for (int o = 0; o < 32; o++) ws[o] = 0.f;
    if (row >= NB) return;
    float r = row * (3.0f / NB);
    float f[10];
#pragma unroll
    for (int k = 0; k < 10; k++) {
        float c = (k + 1) * (3.0f / 11.0f);
        float d = (r - c) * (11.0f / 3.0f);
        float den = 1.0f - d * d;
        f[k] = (den > 0.f) ? 1.14136f * __expf(2.0f - 2.0f / den) : 0.f;
    }
    float h[16];
#pragma unroll
    for (int c = 0; c < 16; c++) {
        float s = 0.f;
#pragma unroll
        for (int k = 0; k < 10; k++) s += f[k] * sW1[k * 16 + c];
        h[c] = fmaxf(s, 0.f) * 1.4142135623730951f;
    }
#pragma unroll
    for (int c = 0; c < 16; c++)
#pragma unroll
        for (int o = 0; o < 32; o++) ws[o] += h[c] * sW2r[c * 32 + o];
}

// prep: thread -> LUT row; computes ws(row) and ws(row+1), writes permuted
// values + slopes.
__global__ void prep_kernel(const float* __restrict__ W1,
                            const float* __restrict__ W2) {
    __shared__ float sW2r[512];
    __shared__ float sW1[160];
    int tid = threadIdx.x;
    for (int q = tid; q < 512; q += blockDim.x) {
        int c = q >> 5, o = q & 31;
        const float4* p = (const float4*)(W2 + c * 256 + o * 8);
        float4 u0 = __ldg(p), u1 = __ldg(p + 1);
        sW2r[q] = u0.x + u0.y + u0.z + u0.w + u1.x + u1.y + u1.z + u1.w;
    }
    for (int q = tid; q < 160; q += blockDim.x) sW1[q] = W1[q];
    __syncthreads();

    int row = blockIdx.x * blockDim.x + tid;
    if (row >= NROWS) return;
    float wsa[32], wsb[32];
    compute_ws(row, sW1, sW2r, wsa);
    compute_ws(row + 1, sW1, sW2r, wsb);

    const float GS = 0.015625f;            // 0.25/sqrt(HID) * pw/sqrt(16)
    const float GS3 = GS * 1.7320508075688772f;  // scalar P1 (folds sqrt3)
    float* dst = g_LUT + row * 128;
#pragma unroll
    for (int jj = 0; jj < 8; jj++) {
#pragma unroll
        for (int t = 0; t < 4; t++) {
            int m = 4 * jj + t;
            float a0, a1, b0, b1;
            if (m < 8) {
                a0 = wsa[m] * GS;       a1 = wsa[16 + m] * GS3;
                b0 = wsb[m] * GS;       b1 = wsb[16 + m] * GS3;
            } else {
                int u = (m - 8) / 3;
                a0 = wsa[24 + u] * GS;  a1 = wsa[8 + u] * GS;  // k3*sqrt3 = 1
                b0 = wsb[24 + u] * GS;  b1 = wsb[8 + u] * GS;
            }
            int h = t >> 1, tt = t & 1;
            int pos = h * 32 + jj * 4 + tt * 2;
            dst[pos] = a0;
            dst[pos + 1] = a1;
            dst[64 + pos] = b0 - a0;
            dst[64 + pos + 1] = b1 - a1;
        }
    }
}

// ---------------------------------------------------------------------------
// edge kernel (persistent): 8 lanes/edge, 4 edges/warp. Software-pipelined:
// next tile's evec/esrc loads are issued before consuming this tile's
// dependent LUT/feature loads -> one exposed memory latency per iteration.
// ---------------------------------------------------------------------------
__global__ void __launch_bounds__(TPB)
edge_kernel(const float* __restrict__ feat, const float* __restrict__ evec,
            const int* __restrict__ esrc, float* __restrict__ out, int E,
            int ntiles) {
    int tid = threadIdx.x;
    int lane = tid & 31;
    int wid = tid >> 5;
    int grp = lane >> 3;
    int j = lane & 7;

    int i0 = (j + 1) % 3;
    bool scalar_lane = (j < 2);
    bool pA = (i0 == 0), pB = (i0 == 1);

    int estep = gridDim.x * 32;
    int elimit = ntiles * 32;
    int e = blockIdx.x * 32 + wid * 4 + grp;

    float facc = 0.f;

    // prologue prefetch
    bool valid = e < E;
    int ec = valid ? e : 0;
    float ex = __ldg(evec + 3 * ec + 0);
    float ey = __ldg(evec + 3 * ec + 1);
    float ez = __ldg(evec + 3 * ec + 2);
    int idx = __ldg(esrc + ec);

    for (; e < elimit; e += estep) {
        // ---- scalar chain on prefetched regs ----
        float d2 = fmaf(ex, ex, fmaf(ey, ey, ez * ez));
        float inv_r = rsqrtf(d2);
        float r = d2 * inv_r;
        float sh0 = ex * inv_r;   // unit components (sqrt3 folded into LUT)
        float sh1 = ey * inv_r;
        float sh2 = ez * inv_r;
        float S1 = sh0 + sh1 + sh2;

        float t = fminf(r * (NB / 3.0f), (float)NB);
        int irow = (int)t;
        float frac = t - (float)irow;

        // ---- dependent loads ----
        const float4* base = (const float4*)g_LUT + irow * 32 + j;
        float4 v0 = __ldg(base);       // values t=0,1
        float4 v1 = __ldg(base + 8);   // values t=2,3
        float4 s0 = __ldg(base + 16);  // slopes t=0,1
        float4 s1 = __ldg(base + 24);  // slopes t=2,3
        float4 x4 = __ldg((const float4*)feat + (size_t)idx * 8 + j);

        // ---- g selects (uses current sh before prefetch overwrites) ----
        float ga = pA ? sh0 : (pB ? sh1 : sh2);
        float gb = pA ? sh1 : (pB ? sh2 : sh0);
        float gc = pA ? sh2 : (pB ? sh0 : sh1);
        float g0 = scalar_lane ? S1 : ga;
        float g1 = scalar_lane ? S1 : gb;
        float g2 = scalar_lane ? S1 : gc;
        float g3 = scalar_lane ? S1 : ga;
        bool curvalid = valid;

        // ---- prefetch next tile (independent of pending loads) ----
        int ne = e + estep;
        if (ne < elimit) {
            valid = ne < E;
            ec = valid ? ne : 0;
            ex = __ldg(evec + 3 * ec + 0);
            ey = __ldg(evec + 3 * ec + 1);
            ez = __ldg(evec + 3 * ec + 2);
            idx = __ldg(esrc + ec);
        }

        // ---- consume ----
        if (curvalid) {
            float c0, c1;
            c0 = fmaf(frac, s0.x, v0.x);
            c1 = fmaf(frac, s0.y, v0.y);
            facc = fmaf(x4.x, fmaf(c1, g0, c0), facc);
            c0 = fmaf(frac, s0.z, v0.z);
            c1 = fmaf(frac, s0.w, v0.w);
            facc = fmaf(x4.y, fmaf(c1, g1, c0), facc);
            c0 = fmaf(frac, s1.x, v1.x);
            c1 = fmaf(frac, s1.y, v1.y);
            facc = fmaf(x4.z, fmaf(c1, g2, c0), facc);
            c0 = fmaf(frac, s1.z, v1.z);
            c1 = fmaf(frac, s1.w, v1.w);
            facc = fmaf(x4.w, fmaf(c1, g3, c0), facc);
        }
    }

    // ---- reduce: warp -> block -> g_parts; last block finishes ----
    __shared__ double sredd[TPB / 32];
    __shared__ int sflag;
#pragma unroll
    for (int off = 16; off > 0; off >>= 1)
        facc += __shfl_down_sync(0xffffffffu, facc, off);
    if (lane == 0) sredd[wid] = (double)facc;
    __syncthreads();
    if (tid == 0) {
        double b = 0.0;
#pragma unroll
        for (int w = 0; w < TPB / 32; w++) b += sredd[w];
        g_parts[blockIdx.x] = b;
        __threadfence();
        unsigned int prev = atomicAdd(&g_count, 1u);
        sflag = (prev == gridDim.x - 1) ? 1 : 0;
    }
    __syncthreads();
    if (sflag) {
        __threadfence();
        double s = 0.0;
        for (int i = tid; i < gridDim.x; i += TPB)
            s += ((volatile double*)g_parts)[i];
#pragma unroll
        for (int off = 16; off > 0; off >>= 1)
            s += __shfl_down_sync(0xffffffffu, s, off);
        __shared__ double fin[TPB / 32];
        if (lane == 0) fin[wid] = s;
        __syncthreads();
        if (tid == 0) {
            double v = 0.0;
#pragma unroll
            for (int w = 0; w < TPB / 32; w++) v += fin[w];
            out[0] = (float)v;
            g_count = 0;
        }
    }
}

extern "C" void kernel_launch(void* const* d_in, const int* in_sizes, int n_in,
                              void* d_out, int out_size) {
    const float* feat = (const float*)d_in[0];  // (N, 32)
    const float* evec = (const float*)d_in[1];  // (E, 3)
    const float* W1   = (const float*)d_in[2];  // (10, 16)
    const float* W2   = (const float*)d_in[3];  // (16, 256)
    const int*   esrc = (const int*)d_in[4];    // (E,)
    // edge_dst / num_nodes drop out: segment_sum then total sum == sum over
    // edges; radial pipeline collapses to a 1-D (value, slope) LUT in r.
    int E = in_sizes[4];
    int ntiles = (E + 31) / 32;

    prep_kernel<<<(NROWS + 127) / 128, 128>>>(W1, W2);
    edge_kernel<<<GRID_EDGE, TPB>>>(feat, evec, esrc, (float*)d_out, E, ntiles);
}

// round 11
// speedup vs baseline: 1.0631x; 1.0631x over previous
#include <cuda_runtime.h>
#include <cuda_fp16.h>
#include <cstdint>

#define NB 2048
#define NROWS (NB + 2)
#define TPB 256
#define GRID_EDGE 1184

__device__ double g_parts[2048];
__device__ unsigned int g_count = 0;
// fp16 LUT row = 64 half2 words (256B), interleaved per lane j (0..7):
//   words [8j .. 8j+4)   = (P0,P1) values for elements m = 4j+t, t=0..3
//   words [8j+4 .. 8j+8) = slopes (next row - this row) for the same m
// with:
//   m <  8: P0 = ws[m]·GS,        P1 = ws[16+m]·GS·sqrt3   (g = S1)
//   m >= 8: u=(m-8)/3: P0 = ws[24+u]·GS, P1 = ws[8+u]·GS   (g = unit[(m-8)%3])
__device__ __align__(16) __half2 g_LUTh[NROWS * 64];

// ---------------------------------------------------------------------------
// warp-cooperative ws row: lane o returns ws[o](row). rows >= NB give 0.
// ---------------------------------------------------------------------------
__device__ __forceinline__ float row_ws(int row, int lane, const float* sW1,
                                        const float* sW2r) {
    float f = 0.f;
    if (row < NB && lane < 10) {
        float r = row * (3.0f / NB);
        float c = (lane + 1) * (3.0f / 11.0f);
        float d = (r - c) * (11.0f / 3.0f);
        float den = 1.0f - d * d;
        f = (den > 0.f) ? 1.14136f * __expf(2.0f - 2.0f / den) : 0.f;
    }
    float h = 0.f;
#pragma unroll
    for (int k = 0; k < 10; k++)
        h = fmaf(__shfl_sync(0xffffffffu, f, k), sW1[k * 16 + (lane & 15)], h);
    h = fmaxf(h, 0.f) * 1.4142135623730951f;
    float ws = 0.f;
#pragma unroll
    for (int c = 0; c < 16; c++)
        ws = fmaf(__shfl_sync(0xffffffffu, h, c), sW2r[c * 32 + lane], ws);
    return ws;
}

// prep: block handles 32 LUT rows (+1 overlap). Warps build raw ws rows in
// smem cooperatively, then threads permute/scale/pack fp16 value+slope words.
__global__ void __launch_bounds__(TPB)
prep_kernel(const float* __restrict__ W1, const float* __restrict__ W2) {
    __shared__ float sW2r[512];
    __shared__ float sW1[160];
    __shared__ float sws[33][33];  // padded stride vs bank conflicts

    int tid = threadIdx.x;
    int lane = tid & 31;
    int wid = tid >> 5;

    for (int q = tid; q < 512; q += TPB) {
        int c = q >> 5, o = q & 31;
        const float4* p = (const float4*)(W2 + c * 256 + o * 8);
        float4 u0 = __ldg(p), u1 = __ldg(p + 1);
        sW2r[q] = u0.x + u0.y + u0.z + u0.w + u1.x + u1.y + u1.z + u1.w;
    }
    for (int q = tid; q < 160; q += TPB) sW1[q] = W1[q];
    __syncthreads();

    int rbase = blockIdx.x * 32;
#pragma unroll
    for (int k = 0; k < 5; k++) {
        int rl = wid + 8 * k;
        if (rl <= 32) sws[rl][lane] = row_ws(rbase + rl, lane, sW1, sW2r);
    }
    __syncthreads();

    const float GS = 0.015625f;                  // 0.25/sqrt(HID)*pw/sqrt(16)
    const float GS3 = GS * 1.7320508075688772f;  // scalar P1 (folds sqrt3)
    for (int item = tid; item < 1024; item += TPB) {
        int rl = item >> 5, m = item & 31;
        int row = rbase + rl;
        if (row >= NROWS) continue;
        int o0, o1;
        float s1;
        if (m < 8) { o0 = m; o1 = 16 + m; s1 = GS3; }
        else { int u = (m - 8) / 3; o0 = 24 + u; o1 = 8 + u; s1 = GS; }
        float a0 = sws[rl][o0] * GS, a1 = sws[rl][o1] * s1;
        float b0 = sws[rl + 1][o0] * GS, b1 = sws[rl + 1][o1] * s1;
        int j = m >> 2, t = m & 3;
        // interleaved layout: value word 8j+t, slope word 8j+4+t
        g_LUTh[row * 64 + 8 * j + t] = __floats2half2_rn(a0, a1);
        g_LUTh[row * 64 + 8 * j + 4 + t] =
            __floats2half2_rn(b0 - a0, b1 - a1);
    }
}

// ---------------------------------------------------------------------------
// edge kernel (persistent): 8 lanes/edge, 4 edges/warp, software-pipelined
// evec/esrc prefetch. fp16 LUT: 2 LDG.128 -> 4 HFMA2 lerps -> fp32 dot.
// ---------------------------------------------------------------------------
__global__ void __launch_bounds__(TPB)
edge_kernel(const float* __restrict__ feat, const float* __restrict__ evec,
            const int* __restrict__ esrc, float* __restrict__ out, int E,
            int ntiles) {
    int tid = threadIdx.x;
    int lane = tid & 31;
    int wid = tid >> 5;
    int grp = lane >> 3;
    int j = lane & 7;

    int i0 = (j + 1) % 3;
    bool scalar_lane = (j < 2);
    bool pA = (i0 == 0), pB = (i0 == 1);

    int estep = gridDim.x * 32;
    int elimit = ntiles * 32;
    int e = blockIdx.x * 32 + wid * 4 + grp;

    float facc = 0.f;

    bool valid = e < E;
    int ec = valid ? e : 0;
    float ex = __ldg(evec + 3 * ec + 0);
    float ey = __ldg(evec + 3 * ec + 1);
    float ez = __ldg(evec + 3 * ec + 2);
    int idx = __ldg(esrc + ec);

    for (; e < elimit; e += estep) {
        float d2 = fmaf(ex, ex, fmaf(ey, ey, ez * ez));
        float inv_r = rsqrtf(d2);
        float r = d2 * inv_r;
        float sh0 = ex * inv_r;  // unit components (sqrt3 folded into LUT)
        float sh1 = ey * inv_r;
        float sh2 = ez * inv_r;
        float S1 = sh0 + sh1 + sh2;

        float t = fminf(r * (NB / 3.0f), (float)NB);
        int irow = (int)t;
        float frac = t - (float)irow;

        // lane j reads its interleaved 32B (value uint4, slope uint4) pair
        const uint4* lb = (const uint4*)g_LUTh + irow * 16 + 2 * j;
        uint4 hv = __ldg(lb);      // 4 half2 values (P0,P1), t=0..3
        uint4 hs = __ldg(lb + 1);  // 4 half2 slopes
        float4 x4 = __ldg((const float4*)feat + (size_t)idx * 8 + j);

        float ga = pA ? sh0 : (pB ? sh1 : sh2);
        float gb = pA ? sh1 : (pB ? sh2 : sh0);
        float gc = pA ? sh2 : (pB ? sh0 : sh1);
        float g0 = scalar_lane ? S1 : ga;
        float g1 = scalar_lane ? S1 : gb;
        float g2 = scalar_lane ? S1 : gc;
        float g3 = scalar_lane ? S1 : ga;
        bool curvalid = valid;

        // prefetch next tile (independent of pending loads)
        int ne = e + estep;
        if (ne < elimit) {
            valid = ne < E;
            ec = valid ? ne : 0;
            ex = __ldg(evec + 3 * ec + 0);
            ey = __ldg(evec + 3 * ec + 1);
            ez = __ldg(evec + 3 * ec + 2);
            idx = __ldg(esrc + ec);
        }

        if (curvalid) {
            __half2 fr2 = __float2half2_rn(frac);
            __half2 c2;
            float2 cf;
            c2 = __hfma2(fr2, *(const __half2*)&hs.x, *(const __half2*)&hv.x);
            cf = __half22float2(c2);
            facc = fmaf(x4.x, fmaf(cf.y, g0, cf.x), facc);
            c2 = __hfma2(fr2, *(const __half2*)&hs.y, *(const __half2*)&hv.y);
            cf = __half22float2(c2);
            facc = fmaf(x4.y, fmaf(cf.y, g1, cf.x), facc);
            c2 = __hfma2(fr2, *(const __half2*)&hs.z, *(const __half2*)&hv.z);
            cf = __half22float2(c2);
            facc = fmaf(x4.z, fmaf(cf.y, g2, cf.x), facc);
            c2 = __hfma2(fr2, *(const __half2*)&hs.w, *(const __half2*)&hv.w);
            cf = __half22float2(c2);
            facc = fmaf(x4.w, fmaf(cf.y, g3, cf.x), facc);
        }
    }

    // ---- reduce: warp -> block -> g_parts; last block finishes ----
    __shared__ double sredd[TPB / 32];
    __shared__ int sflag;
#pragma unroll
    for (int off = 16; off > 0; off >>= 1)
        facc += __shfl_down_sync(0xffffffffu, facc, off);
    if (lane == 0) sredd[wid] = (double)facc;
    __syncthreads();
    if (tid == 0) {
        double b = 0.0;
#pragma unroll
        for (int w = 0; w < TPB / 32; w++) b += sredd[w];
        g_parts[blockIdx.x] = b;
        __threadfence();
        unsigned int prev = atomicAdd(&g_count, 1u);
        sflag = (prev == gridDim.x - 1) ? 1 : 0;
    }
    __syncthreads();
    if (sflag) {
        __threadfence();
        double s = 0.0;
        for (int i = tid; i < gridDim.x; i += TPB)
            s += ((volatile double*)g_parts)[i];
#pragma unroll
        for (int off = 16; off > 0; off >>= 1)
            s += __shfl_down_sync(0xffffffffu, s, off);
        __shared__ double fin[TPB / 32];
        if (lane == 0) fin[wid] = s;
        __syncthreads();
        if (tid == 0) {
            double v = 0.0;
#pragma unroll
            for (int w = 0; w < TPB / 32; w++) v += fin[w];
            out[0] = (float)v;
            g_count = 0;
        }
    }
}

extern "C" void kernel_launch(void* const* d_in, const int* in_sizes, int n_in,
                              void* d_out, int out_size) {
    const float* feat = (const float*)d_in[0];  // (N, 32)
    const float* evec = (const float*)d_in[1];  // (E, 3)
    const float* W1   = (const float*)d_in[2];  // (10, 16)
    const float* W2   = (const float*)d_in[3];  // (16, 256)
    const int*   esrc = (const int*)d_in[4];    // (E,)
    // edge_dst / num_nodes drop out: segment_sum then total sum == sum over
    // edges; radial pipeline collapses to a 1-D (value, slope) fp16 LUT in r.
    int E = in_sizes[4];
    int ntiles = (E + 31) / 32;

    prep_kernel<<<(NROWS + 31) / 32, TPB>>>(W1, W2);
    edge_kernel<<<GRID_EDGE, TPB>>>(feat, evec, esrc, (float*)d_out, E, ntiles);
}

// round 12
// speedup vs baseline: 1.0826x; 1.0183x over previous
#include <cuda_runtime.h>
#include <cuda_fp16.h>
#include <cstdint>

#define NB 2048
#define NROWS (NB + 2)
#define TPB 256
#define GRID_EDGE 1184

__device__ double g_parts[2048];
__device__ unsigned int g_count = 0;
// fp16 LUT row = 64 half2 words (256B), interleaved per lane j (0..7):
//   words [8j .. 8j+4)   = (P0,P1) values for elements m = 4j+t, t=0..3
//   words [8j+4 .. 8j+8) = slopes (next row - this row) for the same m
// with:
//   m <  8: P0 = ws[m]·GS,        P1 = ws[16+m]·GS·sqrt3   (g = S1)
//   m >= 8: u=(m-8)/3: P0 = ws[24+u]·GS, P1 = ws[8+u]·GS   (g = unit[(m-8)%3])
__device__ __align__(16) __half2 g_LUTh[NROWS * 64];

// ---------------------------------------------------------------------------
// prep: block covers 128 LUT rows (+1 overlap row for slopes).
// Thread-per-row ws computation (independent FMAs, throughput-bound),
// staged in smem, then permuted/scaled/packed to interleaved fp16.
// ---------------------------------------------------------------------------
__global__ void __launch_bounds__(TPB)
prep_kernel(const float* __restrict__ W1, const float* __restrict__ W2) {
    __shared__ float sW2r[512];
    __shared__ float sW1[160];
    __shared__ float sws[129][33];  // padded stride vs bank conflicts

    int tid = threadIdx.x;
    for (int q = tid; q < 512; q += TPB) {
        int c = q >> 5, o = q & 31;
        const float4* p = (const float4*)(W2 + c * 256 + o * 8);
        float4 u0 = __ldg(p), u1 = __ldg(p + 1);
        sW2r[q] = u0.x + u0.y + u0.z + u0.w + u1.x + u1.y + u1.z + u1.w;
    }
    for (int q = tid; q < 160; q += TPB) sW1[q] = W1[q];
    __syncthreads();

    int rbase = blockIdx.x * 128;
    if (tid <= 128) {
        int row = rbase + tid;
        float ws[32];
#pragma unroll
        for (int o = 0; o < 32; o++) ws[o] = 0.f;
        if (row < NB) {
            float r = row * (3.0f / NB);
            float f[10];
#pragma unroll
            for (int k = 0; k < 10; k++) {
                float c = (k + 1) * (3.0f / 11.0f);
                float d = (r - c) * (11.0f / 3.0f);
                float den = 1.0f - d * d;
                f[k] = (den > 0.f) ? 1.14136f * __expf(2.0f - 2.0f / den)
                                   : 0.f;
            }
            float h[16];
#pragma unroll
            for (int c = 0; c < 16; c++) {
                float s = 0.f;
#pragma unroll
                for (int k = 0; k < 10; k++) s += f[k] * sW1[k * 16 + c];
                h[c] = fmaxf(s, 0.f) * 1.4142135623730951f;
            }
#pragma unroll
            for (int c = 0; c < 16; c++)
#pragma unroll
                for (int o = 0; o < 32; o++) ws[o] += h[c] * sW2r[c * 32 + o];
        }
#pragma unroll
        for (int o = 0; o < 32; o++) sws[tid][o] = ws[o];
    }
    __syncthreads();

    const float GS = 0.015625f;                  // 0.25/sqrt(HID)*pw/sqrt(16)
    const float GS3 = GS * 1.7320508075688772f;  // scalar P1 (folds sqrt3)
    for (int item = tid; item < 128 * 32; item += TPB) {
        int rl = item >> 5, m = item & 31;
        int row = rbase + rl;
        if (row >= NROWS) continue;
        int o0, o1;
        float s1;
        if (m < 8) { o0 = m; o1 = 16 + m; s1 = GS3; }
        else { int u = (m - 8) / 3; o0 = 24 + u; o1 = 8 + u; s1 = GS; }
        float a0 = sws[rl][o0] * GS, a1 = sws[rl][o1] * s1;
        float b0 = sws[rl + 1][o0] * GS, b1 = sws[rl + 1][o1] * s1;
        int j = m >> 2, t = m & 3;
        g_LUTh[row * 64 + 8 * j + t] = __floats2half2_rn(a0, a1);
        g_LUTh[row * 64 + 8 * j + 4 + t] =
            __floats2half2_rn(b0 - a0, b1 - a1);
    }
}

// ---------------------------------------------------------------------------
// edge kernel (persistent): 8 lanes/edge, 4 edges/warp. Deep software
// pipeline: evec/esrc AND the feature row are prefetched one iteration
// ahead; only the LUT load chain is exposed per iteration.
// ---------------------------------------------------------------------------
__global__ void __launch_bounds__(TPB)
edge_kernel(const float* __restrict__ feat, const float* __restrict__ evec,
            const int* __restrict__ esrc, float* __restrict__ out, int E,
            int ntiles) {
    int tid = threadIdx.x;
    int lane = tid & 31;
    int wid = tid >> 5;
    int grp = lane >> 3;
    int j = lane & 7;

    int i0 = (j + 1) % 3;
    bool scalar_lane = (j < 2);
    bool pA = (i0 == 0), pB = (i0 == 1);

    int estep = gridDim.x * 32;
    int elimit = ntiles * 32;
    int e = blockIdx.x * 32 + wid * 4 + grp;

    float facc = 0.f;

    // prologue prefetch: edge vec, src index, and the feature row
    bool valid = e < E;
    int ec = valid ? e : 0;
    float ex = __ldg(evec + 3 * ec + 0);
    float ey = __ldg(evec + 3 * ec + 1);
    float ez = __ldg(evec + 3 * ec + 2);
    int idx = __ldg(esrc + ec);
    float4 x4 = __ldg((const float4*)feat + (size_t)idx * 8 + j);

    for (; e < elimit; e += estep) {
        float d2 = fmaf(ex, ex, fmaf(ey, ey, ez * ez));
        float inv_r = rsqrtf(d2);
        float r = d2 * inv_r;
        float sh0 = ex * inv_r;  // unit components (sqrt3 folded into LUT)
        float sh1 = ey * inv_r;
        float sh2 = ez * inv_r;
        float S1 = sh0 + sh1 + sh2;

        float t = fminf(r * (NB / 3.0f), (float)NB);
        int irow = (int)t;
        float frac = t - (float)irow;

        // lane j reads its interleaved 32B (value uint4, slope uint4) pair
        const uint4* lb = (const uint4*)g_LUTh + irow * 16 + 2 * j;
        uint4 hv = __ldg(lb);      // 4 half2 values (P0,P1), t=0..3
        uint4 hs = __ldg(lb + 1);  // 4 half2 slopes

        float ga = pA ? sh0 : (pB ? sh1 : sh2);
        float gb = pA ? sh1 : (pB ? sh2 : sh0);
        float gc = pA ? sh2 : (pB ? sh0 : sh1);
        float g0 = scalar_lane ? S1 : ga;
        float g1 = scalar_lane ? S1 : gb;
        float g2 = scalar_lane ? S1 : gc;
        float g3 = scalar_lane ? S1 : ga;
        bool curvalid = valid;
        float4 xc = x4;

        // prefetch next tile (independent of pending LUT loads)
        int ne = e + estep;
        if (ne < elimit) {
            valid = ne < E;
            ec = valid ? ne : 0;
            ex = __ldg(evec + 3 * ec + 0);
            ey = __ldg(evec + 3 * ec + 1);
            ez = __ldg(evec + 3 * ec + 2);
            idx = __ldg(esrc + ec);
            x4 = __ldg((const float4*)feat + (size_t)idx * 8 + j);
        }

        if (curvalid) {
            __half2 fr2 = __float2half2_rn(frac);
            __half2 c2;
            float2 cf;
            c2 = __hfma2(fr2, *(const __half2*)&hs.x, *(const __half2*)&hv.x);
            cf = __half22float2(c2);
            facc = fmaf(xc.x, fmaf(cf.y, g0, cf.x), facc);
            c2 = __hfma2(fr2, *(const __half2*)&hs.y, *(const __half2*)&hv.y);
            cf = __half22float2(c2);
            facc = fmaf(xc.y, fmaf(cf.y, g1, cf.x), facc);
            c2 = __hfma2(fr2, *(const __half2*)&hs.z, *(const __half2*)&hv.z);
            cf = __half22float2(c2);
            facc = fmaf(xc.z, fmaf(cf.y, g2, cf.x), facc);
            c2 = __hfma2(fr2, *(const __half2*)&hs.w, *(const __half2*)&hv.w);
            cf = __half22float2(c2);
            facc = fmaf(xc.w, fmaf(cf.y, g3, cf.x), facc);
        }
    }

    // ---- reduce: warp -> block -> g_parts; last block finishes ----
    __shared__ double sredd[TPB / 32];
    __shared__ int sflag;
#pragma unroll
    for (int off = 16; off > 0; off >>= 1)
        facc += __shfl_down_sync(0xffffffffu, facc, off);
    if (lane == 0) sredd[wid] = (double)facc;
    __syncthreads();
    if (tid == 0) {
        double b = 0.0;
#pragma unroll
        for (int w = 0; w < TPB / 32; w++) b += sredd[w];
        g_parts[blockIdx.x] = b;
        __threadfence();
        unsigned int prev = atomicAdd(&g_count, 1u);
        sflag = (prev == gridDim.x - 1) ? 1 : 0;
    }
    __syncthreads();
    if (sflag) {
        __threadfence();
        double s = 0.0;
        for (int i = tid; i < gridDim.x; i += TPB)
            s += ((volatile double*)g_parts)[i];
#pragma unroll
        for (int off = 16; off > 0; off >>= 1)
            s += __shfl_down_sync(0xffffffffu, s, off);
        __shared__ double fin[TPB / 32];
        if (lane == 0) fin[wid] = s;
        __syncthreads();
        if (tid == 0) {
            double v = 0.0;
#pragma unroll
            for (int w = 0; w < TPB / 32; w++) v += fin[w];
            out[0] = (float)v;
            g_count = 0;
        }
    }
}

extern "C" void kernel_launch(void* const* d_in, const int* in_sizes, int n_in,
                              void* d_out, int out_size) {
    const float* feat = (const float*)d_in[0];  // (N, 32)
    const float* evec = (const float*)d_in[1];  // (E, 3)
    const float* W1   = (const float*)d_in[2];  // (10, 16)
    const float* W2   = (const float*)d_in[3];  // (16, 256)
    const int*   esrc = (const int*)d_in[4];    // (E,)
    // edge_dst / num_nodes drop out: segment_sum then total sum == sum over
    // edges; radial pipeline collapses to a 1-D (value, slope) fp16 LUT in r.
    int E = in_sizes[4];
    int ntiles = (E + 31) / 32;

    prep_kernel<<<(NROWS + 127) / 128, TPB>>>(W1, W2);
    edge_kernel<<<GRID_EDGE, TPB>>>(feat, evec, esrc, (float*)d_out, E, ntiles);
}

// round 13
// speedup vs baseline: 1.1258x; 1.0399x over previous
#include <cuda_runtime.h>
#include <cuda_fp16.h>
#include <cstdint>

#define NB 2048
#define NROWS (NB + 2)
#define TPB 256
#define GRID_EDGE 1184

__device__ double g_parts[2048];
__device__ unsigned int g_count = 0;
// fp16 LUT row = 64 half2 words (256B), interleaved per lane j (0..7):
//   words [8j .. 8j+4)   = (P0,P1) values for elements m = 4j+t, t=0..3
//   words [8j+4 .. 8j+8) = slopes (next row - this row) for the same m
// with:
//   m <  8: P0 = ws[m]·GS,        P1 = ws[16+m]·GS·sqrt3   (g = S1)
//   m >= 8: u=(m-8)/3: P0 = ws[24+u]·GS, P1 = ws[8+u]·GS   (g = unit[(m-8)%3])
__device__ __align__(16) __half2 g_LUTh[NROWS * 64];

// ---------------------------------------------------------------------------
// prep: block covers 128 LUT rows (+1 overlap row for slopes).
// Thread-per-row ws computation (independent FMAs, throughput-bound),
// staged in smem, then permuted/scaled/packed to interleaved fp16.
// ---------------------------------------------------------------------------
__global__ void __launch_bounds__(TPB)
prep_kernel(const float* __restrict__ W1, const float* __restrict__ W2) {
    __shared__ float sW2r[512];
    __shared__ float sW1[160];
    __shared__ float sws[129][33];  // padded stride vs bank conflicts

    int tid = threadIdx.x;
    for (int q = tid; q < 512; q += TPB) {
        int c = q >> 5, o = q & 31;
        const float4* p = (const float4*)(W2 + c * 256 + o * 8);
        float4 u0 = __ldg(p), u1 = __ldg(p + 1);
        sW2r[q] = u0.x + u0.y + u0.z + u0.w + u1.x + u1.y + u1.z + u1.w;
    }
    for (int q = tid; q < 160; q += TPB) sW1[q] = W1[q];
    __syncthreads();

    int rbase = blockIdx.x * 128;
    if (tid <= 128) {
        int row = rbase + tid;
        float ws[32];
#pragma unroll
        for (int o = 0; o < 32; o++) ws[o] = 0.f;
        if (row < NB) {
            float r = row * (3.0f / NB);
            float f[10];
#pragma unroll
            for (int k = 0; k < 10; k++) {
                float c = (k + 1) * (3.0f / 11.0f);
                float d = (r - c) * (11.0f / 3.0f);
                float den = 1.0f - d * d;
                f[k] = (den > 0.f) ? 1.14136f * __expf(2.0f - 2.0f / den)
                                   : 0.f;
            }
            float h[16];
#pragma unroll
            for (int c = 0; c < 16; c++) {
                float s = 0.f;
#pragma unroll
                for (int k = 0; k < 10; k++) s += f[k] * sW1[k * 16 + c];
                h[c] = fmaxf(s, 0.f) * 1.4142135623730951f;
            }
#pragma unroll
            for (int c = 0; c < 16; c++)
#pragma unroll
                for (int o = 0; o < 32; o++) ws[o] += h[c] * sW2r[c * 32 + o];
        }
#pragma unroll
        for (int o = 0; o < 32; o++) sws[tid][o] = ws[o];
    }
    __syncthreads();

    const float GS = 0.015625f;                  // 0.25/sqrt(HID)*pw/sqrt(16)
    const float GS3 = GS * 1.7320508075688772f;  // scalar P1 (folds sqrt3)
    for (int item = tid; item < 128 * 32; item += TPB) {
        int rl = item >> 5, m = item & 31;
        int row = rbase + rl;
        if (row >= NROWS) continue;
        int o0, o1;
        float s1;
        if (m < 8) { o0 = m; o1 = 16 + m; s1 = GS3; }
        else { int u = (m - 8) / 3; o0 = 24 + u; o1 = 8 + u; s1 = GS; }
        float a0 = sws[rl][o0] * GS, a1 = sws[rl][o1] * s1;
        float b0 = sws[rl + 1][o0] * GS, b1 = sws[rl + 1][o1] * s1;
        int j = m >> 2, t = m & 3;
        g_LUTh[row * 64 + 8 * j + t] = __floats2half2_rn(a0, a1);
        g_LUTh[row * 64 + 8 * j + 4 + t] =
            __floats2half2_rn(b0 - a0, b1 - a1);
    }
}

// ---------------------------------------------------------------------------
// edge kernel (persistent): 8 lanes/edge, 4 edges/warp. 2-deep software
// pipeline: iteration i consumes tile i, issues the feature load for tile
// i+1 (index loaded during iteration i-1 — already landed), and issues
// ev/idx loads for tile i+2. No intra-iteration load->load dependency.
// ---------------------------------------------------------------------------
__global__ void __launch_bounds__(TPB)
edge_kernel(const float* __restrict__ feat, const float* __restrict__ evec,
            const int* __restrict__ esrc, float* __restrict__ out, int E,
            int ntiles) {
    int tid = threadIdx.x;
    int lane = tid & 31;
    int wid = tid >> 5;
    int grp = lane >> 3;
    int j = lane & 7;

    int i0 = (j + 1) % 3;
    bool scalar_lane = (j < 2);
    bool pA = (i0 == 0), pB = (i0 == 1);

    int estep = gridDim.x * 32;
    int elimit = ntiles * 32;
    int e = blockIdx.x * 32 + wid * 4 + grp;

    float facc = 0.f;

    // -------- prologue: fill both pipeline stages --------
    // tile i   (current): ev_cur, x4_cur
    // tile i+1 (next):    ev_nxt, idx_nxt
    bool vcur = e < E;
    int ec = vcur ? e : 0;
    float exc = __ldg(evec + 3 * ec + 0);
    float eyc = __ldg(evec + 3 * ec + 1);
    float ezc = __ldg(evec + 3 * ec + 2);
    int idxc = __ldg(esrc + ec);
    float4 x4c = __ldg((const float4*)feat + (size_t)idxc * 8 + j);

    int ne = e + estep;
    bool vnxt = (ne < elimit) && (ne < E);
    int ecn = vnxt ? ne : 0;
    float exn = __ldg(evec + 3 * ecn + 0);
    float eyn = __ldg(evec + 3 * ecn + 1);
    float ezn = __ldg(evec + 3 * ecn + 2);
    int idxn = __ldg(esrc + ecn);

    for (; e < elimit; e += estep) {
        // ---- scalar chain on current tile ----
        float d2 = fmaf(exc, exc, fmaf(eyc, eyc, ezc * ezc));
        float inv_r = rsqrtf(d2);
        float r = d2 * inv_r;
        float sh0 = exc * inv_r;  // unit components (sqrt3 folded into LUT)
        float sh1 = eyc * inv_r;
        float sh2 = ezc * inv_r;
        float S1 = sh0 + sh1 + sh2;

        float t = fminf(r * (NB / 3.0f), (float)NB);
        int irow = (int)t;
        float frac = t - (float)irow;

        // ---- dependent LUT loads for current tile ----
        const uint4* lb = (const uint4*)g_LUTh + irow * 16 + 2 * j;
        uint4 hv = __ldg(lb);      // 4 half2 values (P0,P1), t=0..3
        uint4 hs = __ldg(lb + 1);  // 4 half2 slopes

        float ga = pA ? sh0 : (pB ? sh1 : sh2);
        float gb = pA ? sh1 : (pB ? sh2 : sh0);
        float gc = pA ? sh2 : (pB ? sh0 : sh1);
        float g0 = scalar_lane ? S1 : ga;
        float g1 = scalar_lane ? S1 : gb;
        float g2 = scalar_lane ? S1 : gc;
        float g3 = scalar_lane ? S1 : ga;
        bool curvalid = vcur;
        float4 xc = x4c;

        // ---- stage 1: feature load for tile i+1 (idx landed last iter) ----
        x4c = __ldg((const float4*)feat + (size_t)idxn * 8 + j);

        // ---- rotate ev state, stage 2: ev/idx for tile i+2 ----
        exc = exn; eyc = eyn; ezc = ezn;
        vcur = vnxt;
        int nn = e + 2 * estep;
        if (nn < elimit) {
            vnxt = nn < E;
            int ecn2 = vnxt ? nn : 0;
            exn = __ldg(evec + 3 * ecn2 + 0);
            eyn = __ldg(evec + 3 * ecn2 + 1);
            ezn = __ldg(evec + 3 * ecn2 + 2);
            idxn = __ldg(esrc + ecn2);
        } else {
            vnxt = false;
            idxn = 0;
        }

        // ---- consume current tile ----
        if (curvalid) {
            __half2 fr2 = __float2half2_rn(frac);
            __half2 c2;
            float2 cf;
            c2 = __hfma2(fr2, *(const __half2*)&hs.x, *(const __half2*)&hv.x);
            cf = __half22float2(c2);
            facc = fmaf(xc.x, fmaf(cf.y, g0, cf.x), facc);
            c2 = __hfma2(fr2, *(const __half2*)&hs.y, *(const __half2*)&hv.y);
            cf = __half22float2(c2);
            facc = fmaf(xc.y, fmaf(cf.y, g1, cf.x), facc);
            c2 = __hfma2(fr2, *(const __half2*)&hs.z, *(const __half2*)&hv.z);
            cf = __half22float2(c2);
            facc = fmaf(xc.z, fmaf(cf.y, g2, cf.x), facc);
            c2 = __hfma2(fr2, *(const __half2*)&hs.w, *(const __half2*)&hv.w);
            cf = __half22float2(c2);
            facc = fmaf(xc.w, fmaf(cf.y, g3, cf.x), facc);
        }
    }

    // ---- reduce: warp -> block -> g_parts; last block finishes ----
    __shared__ double sredd[TPB / 32];
    __shared__ int sflag;
#pragma unroll
    for (int off = 16; off > 0; off >>= 1)
        facc += __shfl_down_sync(0xffffffffu, facc, off);
    if (lane == 0) sredd[wid] = (double)facc;
    __syncthreads();
    if (tid == 0) {
        double b = 0.0;
#pragma unroll
        for (int w = 0; w < TPB / 32; w++) b += sredd[w];
        g_parts[blockIdx.x] = b;
        __threadfence();
        unsigned int prev = atomicAdd(&g_count, 1u);
        sflag = (prev == gridDim.x - 1) ? 1 : 0;
    }
    __syncthreads();
    if (sflag) {
        __threadfence();
        double s = 0.0;
        for (int i = tid; i < gridDim.x; i += TPB)
            s += ((volatile double*)g_parts)[i];
#pragma unroll
        for (int off = 16; off > 0; off >>= 1)
            s += __shfl_down_sync(0xffffffffu, s, off);
        __shared__ double fin[TPB / 32];
        if (lane == 0) fin[wid] = s;
        __syncthreads();
        if (tid == 0) {
            double v = 0.0;
#pragma unroll
            for (int w = 0; w < TPB / 32; w++) v += fin[w];
            out[0] = (float)v;
            g_count = 0;
        }
    }
}

extern "C" void kernel_launch(void* const* d_in, const int* in_sizes, int n_in,
                              void* d_out, int out_size) {
    const float* feat = (const float*)d_in[0];  // (N, 32)
    const float* evec = (const float*)d_in[1];  // (E, 3)
    const float* W1   = (const float*)d_in[2];  // (10, 16)
    const float* W2   = (const float*)d_in[3];  // (16, 256)
    const int*   esrc = (const int*)d_in[4];    // (E,)
    // edge_dst / num_nodes drop out: segment_sum then total sum == sum over
    // edges; radial pipeline collapses to a 1-D (value, slope) fp16 LUT in r.
    int E = in_sizes[4];
    int ntiles = (E + 31) / 32;

    prep_kernel<<<(NROWS + 127) / 128, TPB>>>(W1, W2);
    edge_kernel<<<GRID_EDGE, TPB>>>(feat, evec, esrc, (float*)d_out, E, ntiles);
}